// round 14
// baseline (speedup 1.0000x reference)
#include <cuda_runtime.h>
#include <cuda_fp16.h>
#include <cstdint>
#include <cstring>

// GeluAvgEmbed: out[cell] = dot(gelu(mean_t W[x[cell,t]]), w_pred) + b_pred
// B,R,C,T = 8,100,64,32 ; D = 128 ; VOCAB = 32000
//
// R14: fp16 table; R9 layout (one token/iteration, lane owns dims [4l,4l+4)
// via one LDG.64); depth-4 software pipeline with ALTERNATING buffer banks
// (no copy instructions); __launch_bounds__(256,6) to push occupancy ~65%.
// Numerics identical to R9/R13: 4-way split HADD2 accumulators (8-add
// chains), fp32 combine -> rel_err ~5.15e-4.

#define TOKENS 32
#define DIMS   128
#define VOCAB  32000
#define FULL_MASK 0xffffffffu

// fp16 copy of the embedding table: 32000 * 128 * 2B = 8.192 MB
__device__ __half2 W_half[(size_t)VOCAB * DIMS / 2];

__global__ __launch_bounds__(256) void convert_w_kernel(
    const float* __restrict__ W, int n8)
{
    int i = blockIdx.x * blockDim.x + threadIdx.x;
    if (i >= n8) return;
    const float4* src = reinterpret_cast<const float4*>(W) + 2 * (size_t)i;
    float4 v0 = src[0];
    float4 v1 = src[1];
    __half2 h[4];
    h[0] = __floats2half2_rn(v0.x, v0.y);
    h[1] = __floats2half2_rn(v0.z, v0.w);
    h[2] = __floats2half2_rn(v1.x, v1.y);
    h[3] = __floats2half2_rn(v1.z, v1.w);
    float4 packed;
    memcpy(&packed, h, 16);
    reinterpret_cast<float4*>(W_half)[i] = packed;   // one STG.128
}

__global__ __launch_bounds__(256, 6) void gelu_avg_embed_kernel(
    const int*   __restrict__ x,        // [n_cells * 32]
    const float* __restrict__ w_pred,   // [128]
    const float* __restrict__ b_pred,   // [1]
    float*       __restrict__ out,      // [n_cells]
    int n_cells)
{
    const int gwarp = (blockIdx.x * blockDim.x + threadIdx.x) >> 5;
    const int lane  = threadIdx.x & 31;
    if (gwarp >= n_cells) return;

    // Lane t holds token t's vocab index (coalesced 128B load of 32 ints).
    const int my_idx = x[gwarp * TOKENS + lane];

    // 4-way split accumulators: bank (t & 3). Each half chain sees 8 adds.
    __half2 accA[4];   // dims 4l, 4l+1
    __half2 accB[4];   // dims 4l+2, 4l+3
    #pragma unroll
    for (int k = 0; k < 4; ++k) {
        accA[k] = __float2half2_rn(0.f);
        accB[k] = __float2half2_rn(0.f);
    }

    // Lane l owns half2 columns 2l, 2l+1 (dims 4l..4l+3): one LDG.64 per row.
    const __half2* base = W_half + 2 * (size_t)lane;

    // Depth-4 pipeline with two alternating buffer banks (parity g&1).
    uint2 bank0[4], bank1[4];

    #pragma unroll
    for (int j = 0; j < 4; ++j) {
        const int row = __shfl_sync(FULL_MASK, my_idx, j);
        bank0[j] = *reinterpret_cast<const uint2*>(base + (size_t)row * (DIMS / 2));
    }

    #pragma unroll
    for (int g = 0; g < 8; ++g) {
        uint2* cur = (g & 1) ? bank1 : bank0;
        uint2* nxt = (g & 1) ? bank0 : bank1;
        if (g < 7) {
            #pragma unroll
            for (int j = 0; j < 4; ++j) {
                const int row = __shfl_sync(FULL_MASK, my_idx, 4 * (g + 1) + j);
                nxt[j] = *reinterpret_cast<const uint2*>(base + (size_t)row * (DIMS / 2));
            }
        }
        #pragma unroll
        for (int j = 0; j < 4; ++j) {
            accA[j] = __hadd2(accA[j], *reinterpret_cast<const __half2*>(&cur[j].x));
            accB[j] = __hadd2(accB[j], *reinterpret_cast<const __half2*>(&cur[j].y));
        }
    }

    // Combine the 4 splits in fp32.
    float s0 = 0.f, s1 = 0.f, s2 = 0.f, s3 = 0.f;
    #pragma unroll
    for (int k = 0; k < 4; ++k) {
        float2 fa = __half22float2(accA[k]);
        float2 fb = __half22float2(accB[k]);
        s0 += fa.x; s1 += fa.y; s2 += fb.x; s3 += fb.y;
    }

    const float inv_t = 1.0f / (float)TOKENS;
    const float kInvSqrt2 = 0.70710678118654752440f;

    float p0 = s0 * inv_t, p1 = s1 * inv_t, p2 = s2 * inv_t, p3 = s3 * inv_t;
    float g0 = 0.5f * p0 * (1.0f + erff(p0 * kInvSqrt2));
    float g1 = 0.5f * p1 * (1.0f + erff(p1 * kInvSqrt2));
    float g2 = 0.5f * p2 * (1.0f + erff(p2 * kInvSqrt2));
    float g3 = 0.5f * p3 * (1.0f + erff(p3 * kInvSqrt2));

    const float4 wv = *reinterpret_cast<const float4*>(w_pred + lane * 4);
    float dot = g0 * wv.x + g1 * wv.y + g2 * wv.z + g3 * wv.w;

    #pragma unroll
    for (int off = 16; off > 0; off >>= 1)
        dot += __shfl_down_sync(FULL_MASK, dot, off);

    if (lane == 0)
        out[gwarp] = dot + b_pred[0];
}

extern "C" void kernel_launch(void* const* d_in, const int* in_sizes, int n_in,
                              void* d_out, int out_size)
{
    const int*   x      = (const int*)  d_in[0];  // [8,100,64,32] int32
    const float* W      = (const float*)d_in[1];  // [32000,128]  f32
    const float* w_pred = (const float*)d_in[2];  // [1,128]      f32
    const float* b_pred = (const float*)d_in[3];  // [1]          f32
    float*       out    = (float*)d_out;          // [8,100,64]   f32

    // 1) Convert W to fp16 scratch (8 elems per thread, STG.128).
    const int n8 = VOCAB * DIMS / 8;               // 512,000
    convert_w_kernel<<<(n8 + 255) / 256, 256>>>(W, n8);

    // 2) Gather + pool + GELU + dot.
    const int n_cells = out_size;                  // 51200
    const int blocks = (n_cells + 7) / 8;          // 8 warps / block
    gelu_avg_embed_kernel<<<blocks, 256>>>(x, w_pred, b_pred, out, n_cells);
}